// round 10
// baseline (speedup 1.0000x reference)
#include <cuda_runtime.h>

// LorentzAvgPool2d: x[32,128,128,64] fp32 NHWC -> out[32,64,64,64]
// 2x2/stride-2 avg pool, then Lorentz centroid normalization:
//   inner = -a0^2 + sum_{c>0} a_c^2
//   out   = a * rsqrt(max(|inner|, 1e-8))      (k=1)
//
// R10 = R9 resubmitted verbatim (R9 bench was an infra failure: container
// acquisition, no kernel signal). The R3 empirical optimum — 8-lane group
// per output pixel, 4x front-batched LD.256 per thread, one-shot grid
// 4096x256, default .nc caching — plus the 0.25 factor folded into the
// epilogue scale:
//   avg = sum/4 ; inner(avg) = inner(sum)/16
//   out = sum * 0.25 * rsqrt(max(|inner(sum)|/16, eps))
//
// Explored and rejected: MLP=2 (R7), MLP=8 (R2,R6), 128-bit ld/st (R1,R2),
// persistent grid-stride (R5), block=128 (R8), .cs streaming hints (R2).
// Kernel is pinned at the ~6 TB/s mixed-stream LTS ceiling.

static constexpr int B = 32;
static constexpr int H = 128;
static constexpr int W = 128;
static constexpr int C = 64;
static constexpr int OH = H / 2;
static constexpr int OW = W / 2;
static constexpr int NPIX = B * OH * OW;          // 131072 output pixels
static constexpr float EPS = 1e-8f;

struct F8 { float v0, v1, v2, v3, v4, v5, v6, v7; };

__device__ __forceinline__ F8 ldg256(const float* p) {
    F8 r;
    asm volatile("ld.global.nc.v8.f32 {%0,%1,%2,%3,%4,%5,%6,%7}, [%8];"
                 : "=f"(r.v0), "=f"(r.v1), "=f"(r.v2), "=f"(r.v3),
                   "=f"(r.v4), "=f"(r.v5), "=f"(r.v6), "=f"(r.v7)
                 : "l"(p));
    return r;
}

__device__ __forceinline__ void stg256(float* p, const F8& r) {
    asm volatile("st.global.v8.f32 [%0], {%1,%2,%3,%4,%5,%6,%7,%8};"
                 :: "l"(p),
                    "f"(r.v0), "f"(r.v1), "f"(r.v2), "f"(r.v3),
                    "f"(r.v4), "f"(r.v5), "f"(r.v6), "f"(r.v7)
                 : "memory");
}

__global__ __launch_bounds__(256) void lorentz_avgpool_kernel(
    const float* __restrict__ x, float* __restrict__ out)
{
    const int tid   = blockIdx.x * blockDim.x + threadIdx.x;
    const int group = tid >> 3;            // global output pixel index
    const int lane  = tid & 7;             // 8-channel slice within pixel
    if (group >= NPIX) return;

    const int ow = group & (OW - 1);                    // 0..63
    const int oh = (group >> 6) & (OH - 1);             // 0..63
    const int b  = group >> 12;                         // 0..31

    const int ih = oh * 2;
    const int iw = ow * 2;

    const long base0 = ((long)(b * H + ih) * W + iw) * C;   // row ih
    const long base1 = base0 + (long)W * C;                 // row ih+1
    const int  co    = lane * 8;                            // channel offset

    // 4 independent 256-bit loads (the 2x2 window), front-batched
    const F8 a  = ldg256(x + base0 + co);          // (ih,   iw  )
    const F8 bq = ldg256(x + base0 + C + co);      // (ih,   iw+1)
    const F8 c  = ldg256(x + base1 + co);          // (ih+1, iw  )
    const F8 d  = ldg256(x + base1 + C + co);      // (ih+1, iw+1)

    // window SUM (division by 4 folded into the final scale)
    F8 sum;
    sum.v0 = (a.v0 + bq.v0) + (c.v0 + d.v0);
    sum.v1 = (a.v1 + bq.v1) + (c.v1 + d.v1);
    sum.v2 = (a.v2 + bq.v2) + (c.v2 + d.v2);
    sum.v3 = (a.v3 + bq.v3) + (c.v3 + d.v3);
    sum.v4 = (a.v4 + bq.v4) + (c.v4 + d.v4);
    sum.v5 = (a.v5 + bq.v5) + (c.v5 + d.v5);
    sum.v6 = (a.v6 + bq.v6) + (c.v6 + d.v6);
    sum.v7 = (a.v7 + bq.v7) + (c.v7 + d.v7);

    // partial Lorentz inner product of the SUM; lane 0's channel 0 is the
    // time coordinate
    float s = sum.v0 * sum.v0;
    if (lane == 0) s = -s;
    s += sum.v1 * sum.v1 + sum.v2 * sum.v2 + sum.v3 * sum.v3
       + sum.v4 * sum.v4 + sum.v5 * sum.v5 + sum.v6 * sum.v6
       + sum.v7 * sum.v7;

    // reduce across the 8-lane group
    s += __shfl_xor_sync(0xFFFFFFFFu, s, 1);
    s += __shfl_xor_sync(0xFFFFFFFFu, s, 2);
    s += __shfl_xor_sync(0xFFFFFFFFu, s, 4);

    // inner(avg) = inner(sum)/16 ; avg = sum*0.25
    const float inv = 0.25f * rsqrtf(fmaxf(fabsf(s) * 0.0625f, EPS));

    F8 r;
    r.v0 = sum.v0 * inv; r.v1 = sum.v1 * inv;
    r.v2 = sum.v2 * inv; r.v3 = sum.v3 * inv;
    r.v4 = sum.v4 * inv; r.v5 = sum.v5 * inv;
    r.v6 = sum.v6 * inv; r.v7 = sum.v7 * inv;

    stg256(out + (long)group * C + co, r);
}

extern "C" void kernel_launch(void* const* d_in, const int* in_sizes, int n_in,
                              void* d_out, int out_size)
{
    const float* x = (const float*)d_in[0];
    float* out = (float*)d_out;

    const int threads = 256;
    const int pix_per_block = threads / 8;                // 32
    const int blocks = (NPIX + pix_per_block - 1) / pix_per_block;  // 4096
    lorentz_avgpool_kernel<<<blocks, threads>>>(x, out);
}

// round 11
// speedup vs baseline: 1.0067x; 1.0067x over previous
#include <cuda_runtime.h>

// LorentzAvgPool2d: x[32,128,128,64] fp32 NHWC -> out[32,64,64,64]
// 2x2/stride-2 avg pool, then Lorentz centroid normalization:
//   inner = -a0^2 + sum_{c>0} a_c^2
//   out   = a * rsqrt(max(|inner|, 1e-8))      (k=1)
//
// R11 (FINAL): converged kernel. 8-lane group per output pixel, 4x
// front-batched LD.256 per thread, one-shot grid 4096x256, default .nc
// caching, 0.25 folded into the epilogue scale, dead bounds-guard removed
// (grid exactly covers NPIX).
//
// Exploration summary (kernel time, ncu):
//   R1  4x LD.128, 256thr          26.6us
//   R2  8x LD.128 + .cs            25.9us
//   R3  4x LD.256 (this structure) 24.9us   <- best
//   R5  persistent grid-stride     26.1us (dur 30.7 — real regression)
//   R6  8x LD.256, 2 pixels/group  26.5us
//   R7  2x LD.256, high occ        25.8us
//   R8  block=128                  26.0us
//   R10 = R3 re-run                26.4us -> run-to-run noise ~±1.5us
// All variants give dur_us 28.7-28.8 (harness floor); kernel is pinned at
// the ~6 TB/s mixed-stream LTS ceiling (path-independent; TMA same cap).

static constexpr int B = 32;
static constexpr int H = 128;
static constexpr int W = 128;
static constexpr int C = 64;
static constexpr int OH = H / 2;
static constexpr int OW = W / 2;
static constexpr int NPIX = B * OH * OW;          // 131072 output pixels
static constexpr float EPS = 1e-8f;

struct F8 { float v0, v1, v2, v3, v4, v5, v6, v7; };

__device__ __forceinline__ F8 ldg256(const float* p) {
    F8 r;
    asm volatile("ld.global.nc.v8.f32 {%0,%1,%2,%3,%4,%5,%6,%7}, [%8];"
                 : "=f"(r.v0), "=f"(r.v1), "=f"(r.v2), "=f"(r.v3),
                   "=f"(r.v4), "=f"(r.v5), "=f"(r.v6), "=f"(r.v7)
                 : "l"(p));
    return r;
}

__device__ __forceinline__ void stg256(float* p, const F8& r) {
    asm volatile("st.global.v8.f32 [%0], {%1,%2,%3,%4,%5,%6,%7,%8};"
                 :: "l"(p),
                    "f"(r.v0), "f"(r.v1), "f"(r.v2), "f"(r.v3),
                    "f"(r.v4), "f"(r.v5), "f"(r.v6), "f"(r.v7)
                 : "memory");
}

__global__ __launch_bounds__(256) void lorentz_avgpool_kernel(
    const float* __restrict__ x, float* __restrict__ out)
{
    const int tid   = blockIdx.x * blockDim.x + threadIdx.x;
    const int group = tid >> 3;            // global output pixel index
    const int lane  = tid & 7;             // 8-channel slice within pixel
    // grid exactly covers NPIX (4096 blocks x 32 pixels) — no bounds guard

    const int ow = group & (OW - 1);                    // 0..63
    const int oh = (group >> 6) & (OH - 1);             // 0..63
    const int b  = group >> 12;                         // 0..31

    const int ih = oh * 2;
    const int iw = ow * 2;

    const long base0 = ((long)(b * H + ih) * W + iw) * C;   // row ih
    const long base1 = base0 + (long)W * C;                 // row ih+1
    const int  co    = lane * 8;                            // channel offset

    // 4 independent 256-bit loads (the 2x2 window), front-batched
    const F8 a  = ldg256(x + base0 + co);          // (ih,   iw  )
    const F8 bq = ldg256(x + base0 + C + co);      // (ih,   iw+1)
    const F8 c  = ldg256(x + base1 + co);          // (ih+1, iw  )
    const F8 d  = ldg256(x + base1 + C + co);      // (ih+1, iw+1)

    // window SUM (division by 4 folded into the final scale)
    F8 sum;
    sum.v0 = (a.v0 + bq.v0) + (c.v0 + d.v0);
    sum.v1 = (a.v1 + bq.v1) + (c.v1 + d.v1);
    sum.v2 = (a.v2 + bq.v2) + (c.v2 + d.v2);
    sum.v3 = (a.v3 + bq.v3) + (c.v3 + d.v3);
    sum.v4 = (a.v4 + bq.v4) + (c.v4 + d.v4);
    sum.v5 = (a.v5 + bq.v5) + (c.v5 + d.v5);
    sum.v6 = (a.v6 + bq.v6) + (c.v6 + d.v6);
    sum.v7 = (a.v7 + bq.v7) + (c.v7 + d.v7);

    // partial Lorentz inner product of the SUM; lane 0's channel 0 is the
    // time coordinate
    float s = sum.v0 * sum.v0;
    if (lane == 0) s = -s;
    s += sum.v1 * sum.v1 + sum.v2 * sum.v2 + sum.v3 * sum.v3
       + sum.v4 * sum.v4 + sum.v5 * sum.v5 + sum.v6 * sum.v6
       + sum.v7 * sum.v7;

    // reduce across the 8-lane group
    s += __shfl_xor_sync(0xFFFFFFFFu, s, 1);
    s += __shfl_xor_sync(0xFFFFFFFFu, s, 2);
    s += __shfl_xor_sync(0xFFFFFFFFu, s, 4);

    // inner(avg) = inner(sum)/16 ; avg = sum*0.25
    const float inv = 0.25f * rsqrtf(fmaxf(fabsf(s) * 0.0625f, EPS));

    F8 r;
    r.v0 = sum.v0 * inv; r.v1 = sum.v1 * inv;
    r.v2 = sum.v2 * inv; r.v3 = sum.v3 * inv;
    r.v4 = sum.v4 * inv; r.v5 = sum.v5 * inv;
    r.v6 = sum.v6 * inv; r.v7 = sum.v7 * inv;

    stg256(out + (long)group * C + co, r);
}

extern "C" void kernel_launch(void* const* d_in, const int* in_sizes, int n_in,
                              void* d_out, int out_size)
{
    const float* x = (const float*)d_in[0];
    float* out = (float*)d_out;

    const int threads = 256;
    const int pix_per_block = threads / 8;                // 32
    const int blocks = NPIX / pix_per_block;              // 4096, exact
    lorentz_avgpool_kernel<<<blocks, threads>>>(x, out);
}